// round 11
// baseline (speedup 1.0000x reference)
#include <cuda_runtime.h>

#define NV 262144            // 64*64*64
#define BIGF 1e9f

// scratch: [mask m (4)][bc (16)][voxel (NV)]  -> 67 MB
// pass1 writes a signed COMBINED field into mask slots 0..1 (pred, tgt):
//   s = bit ? +d_fg : -d_bg   (exactly one side nonzero per voxel)
// pass23 splits it (fg = max(s,0), bg = max(-s,0)) and expands to 4-mask layout.
__device__ float g_f[64ull * NV];
__device__ float g_acc[64];
__device__ unsigned g_cnt;

__device__ __forceinline__ float warpsum(float v) {
#pragma unroll
    for (int o = 16; o > 0; o >>= 1) v += __shfl_xor_sync(0xffffffffu, v, o);
    return v;
}

// squared dist to nearest set bit of `zeros` (BIGF if none)
__device__ __forceinline__ float dt1(unsigned long long zeros, int x) {
    unsigned long long below = zeros << (63 - x);      // bits <= x
    int dfwd = below ? __clzll((long long)below) : 1000;
    unsigned long long above = zeros >> x;             // bits >= x
    int dbwd = above ? (__ffsll((long long)above) - 1) : 1000;
    int d = min(dfwd, dbwd);
    return (d > 63) ? BIGF : (float)(d * d);
}

// ---------------- pass 1 (axis X) ----------------
// 1024 blocks x 256 threads. Block = one (b,c,y) group of 64 z-lines.
// Phase 1: 256 threads load 16 x's each -> partial masks in smem.
// Phase 2: part = (field pred|tgt) x (x-half). One dt1 per (field,x); single
// SIGNED store serves both fg and bg (complement masks).
__global__ void __launch_bounds__(256) k_pass1(const float* __restrict__ in, const int* __restrict__ tg) {
    if (blockIdx.x == 0) {       // reset accumulators for this replay
        if (threadIdx.x < 64) g_acc[threadIdx.x] = 0.0f;
        if (threadIdx.x == 64) g_cnt = 0u;
    }
    unsigned g = blockIdx.x;                 // (b,c,y)
    unsigned y = g & 63u, c = (g >> 6) & 7u, b = g >> 9;
    unsigned bc = b * 8u + c;
    int t = threadIdx.x;
    int z = t & 63;
    int part = t >> 6;                       // 0..3
    const float* pin = in + (size_t)bc * NV + y * 64u + z;
    const int*   ptg = tg + (size_t)b  * NV + y * 64u + z;

    unsigned m16 = 0u;                       // low 16: pred, high 16: tgt
#pragma unroll
    for (int k = 0; k < 16; ++k) {
        int x = part * 16 + k;
        float v = pin[(size_t)x * 4096];
        int   tt = ptg[(size_t)x * 4096];
        if (v > 0.5f)          m16 |= 1u << k;
        if ((unsigned)tt == c) m16 |= 1u << (16 + k);
    }
    __shared__ unsigned sm[256];
    sm[t] = m16;
    __syncthreads();

    int field = part & 1;                    // 0 = pred, 1 = tgt
    int half  = part >> 1;                   // x in [32*half, 32*half+32)
    unsigned long long m = 0ull;
#pragma unroll
    for (int p = 0; p < 4; ++p) {
        unsigned w = sm[z + p * 64];
        unsigned h16 = field ? (w >> 16) : (w & 0xFFFFu);
        m |= (unsigned long long)h16 << (16 * p);
    }
    // combined signed field lives in mask slot `field` (0=pred, 1=tgt)
    float* o = g_f + (size_t)(field * 16 + bc) * NV + y * 64u + z;
#pragma unroll 4
    for (int k = 0; k < 32; ++k) {
        int x = half * 32 + k;
        bool bit = ((m >> x) & 1ull) != 0ull;
        unsigned long long zz = bit ? ~m : m;        // zeros of the non-trivial side
        float dsq = dt1(zz, x);                      // always > 0
        o[(size_t)x * 4096] = bit ? dsq : -dsq;
    }
}

// ---------------- fused Y+Z min-plus over one (y,z) plane in smem ----------------
// Exact: windowed min, pairs |i-j|<=3 (off^2<=9). If windowed min <= 16 it is
// the true min (outside pairs contribute >= 16); otherwise full-scan fallback.
template<int LSTRIDE, int LANESTRIDE>
__device__ __forceinline__ void pass_line(float* s, int t) {
    int lane = t & 63;           // orthogonal coordinate
    int h = t >> 6;              // 0..3 -> outputs i in [16h, 16h+16)
    float* bp = s + lane * LANESTRIDE;
    int jbase = 16 * h - 3;
    float fv[22];
#pragma unroll
    for (int k = 0; k < 22; ++k) {
        int j = jbase + k;
        fv[k] = (j >= 0 && j < 64) ? bp[j * LSTRIDE] : 3.0e38f;
    }
    float d[16];
#pragma unroll
    for (int a = 0; a < 16; ++a) d[a] = 3.0e38f;
#pragma unroll
    for (int k = 0; k < 14; ++k) {
#pragma unroll
        for (int a = 0; a < 8; ++a) {
            const int off = a + 3 - k;
            if (off * off <= 9) d[a] = fminf(d[a], fv[k] + (float)(off * off));
        }
    }
#pragma unroll
    for (int k = 8; k < 22; ++k) {
#pragma unroll
        for (int a = 8; a < 16; ++a) {
            const int off = a + 3 - k;
            if (off * off <= 9) d[a] = fminf(d[a], fv[k] + (float)(off * off));
        }
    }
    float mxA = d[0], mxB = d[8];
#pragma unroll
    for (int a = 1; a < 8; ++a) { mxA = fmaxf(mxA, d[a]); mxB = fmaxf(mxB, d[a + 8]); }
    if (mxA > 16.0f) {
#pragma unroll 1
        for (int j = 0; j < 64; ++j) {
            float fj = bp[j * LSTRIDE];
#pragma unroll
            for (int a = 0; a < 8; ++a) { int dd = 16 * h + a - j; d[a] = fminf(d[a], fj + (float)(dd * dd)); }
        }
    }
    if (mxB > 16.0f) {
#pragma unroll 1
        for (int j = 0; j < 64; ++j) {
            float fj = bp[j * LSTRIDE];
#pragma unroll
            for (int a = 8; a < 16; ++a) { int dd = 16 * h + a - j; d[a] = fminf(d[a], fj + (float)(dd * dd)); }
        }
    }
    __syncthreads();   // all reads (incl. fallback) done before anyone writes
#pragma unroll
    for (int a = 0; a < 16; ++a) bp[(16 * h + a) * LSTRIDE] = d[a];
    __syncthreads();
}

// 2048 blocks: (combined vol cvol = field*16+bc in 0..31) x (x in 0..63).
// Loads ONE combined signed plane, splits to fg/bg planes in smem, runs the
// Y+Z passes on both, writes the standard 4-mask layout.
__global__ void __launch_bounds__(256) k_pass23() {
    __shared__ float sf[64 * 65];
    __shared__ float sb[64 * 65];
    unsigned x = blockIdx.x & 63u, cvol = blockIdx.x >> 6;   // cvol < 32
    unsigned field = cvol >> 4, bc = cvol & 15u;
    float* gin = g_f + (size_t)cvol * NV + x * 4096u;        // combined plane
    int t = threadIdx.x;
    {
        const float4* g4 = (const float4*)gin;
#pragma unroll
        for (int m = 0; m < 4; ++m) {
            int e4 = m * 256 + t;            // 1024 float4s
            float4 val = g4[e4];
            int e = e4 * 4;
            int y = e >> 6, z = e & 63;
            int idx = y * 65 + z;
            sf[idx + 0] = fmaxf(val.x, 0.0f); sb[idx + 0] = fmaxf(-val.x, 0.0f);
            sf[idx + 1] = fmaxf(val.y, 0.0f); sb[idx + 1] = fmaxf(-val.y, 0.0f);
            sf[idx + 2] = fmaxf(val.z, 0.0f); sb[idx + 2] = fmaxf(-val.z, 0.0f);
            sf[idx + 3] = fmaxf(val.w, 0.0f); sb[idx + 3] = fmaxf(-val.w, 0.0f);
        }
    }
    __syncthreads();
    pass_line<65, 1>(sf, t);   // Y pass, fg
    pass_line<65, 1>(sb, t);   // Y pass, bg
    pass_line<1, 65>(sf, t);   // Z pass, fg
    pass_line<1, 65>(sb, t);   // Z pass, bg
    {
        // fg -> mask slot field (0/1); bg -> mask slot field+2 (2/3)
        float4* gof = (float4*)(g_f + (size_t)(field * 16 + bc) * NV + x * 4096u);
        float4* gob = (float4*)(g_f + (size_t)((field + 2) * 16 + bc) * NV + x * 4096u);
#pragma unroll
        for (int m = 0; m < 4; ++m) {
            int e4 = m * 256 + t;
            int e = e4 * 4;
            int y = e >> 6, z = e & 63;
            int idx = y * 65 + z;
            float4 vf, vb;
            vf.x = sf[idx + 0]; vf.y = sf[idx + 1]; vf.z = sf[idx + 2]; vf.w = sf[idx + 3];
            vb.x = sb[idx + 0]; vb.y = sb[idx + 1]; vb.z = sb[idx + 2]; vb.w = sb[idx + 3];
            gof[e4] = vf;
            gob[e4] = vb;
        }
    }
}

// ---------------- full min-plus over channel axis, length 8, branchless ----------------
__device__ __forceinline__ void minplus8(const float* __restrict__ a, float* __restrict__ d) {
#pragma unroll
    for (int i = 0; i < 8; ++i) {
        float m = 3.0e38f;
#pragma unroll
        for (int j = 0; j < 8; ++j) {
            const float q = (float)((i - j) * (i - j));
            m = fminf(m, a[j] + q);
        }
        d[i] = m;
    }
}

// ---------------- fused stats + HD (+ channel EDT pass) + final ----------------
// 1024 blocks x 256 threads x 2 voxels = 524288 (b, voxel) entries
__global__ void __launch_bounds__(256) k_shd(const float* __restrict__ in, const int* __restrict__ tg,
                                             float* __restrict__ out) {
    unsigned E = (blockIdx.x * 256u + threadIdx.x) * 2u;
    unsigned v = E & (NV - 1u);
    unsigned b = E >> 18;

    float X[2][8];
#pragma unroll
    for (int c = 0; c < 8; ++c) {
        float2 t2 = *(const float2*)(in + (size_t)(b * 8 + c) * NV + v);
        X[0][c] = t2.x; X[1][c] = t2.y;
    }
    int T[2];
    { int2 tt = *(const int2*)(tg + (size_t)b * NV + v); T[0] = tt.x; T[1] = tt.y; }

    float tp[8], sP[8], cn[8];
#pragma unroll
    for (int c = 0; c < 8; ++c) { tp[c] = 0.f; sP[c] = 0.f; cn[c] = 0.f; }
    float ce = 0.0f, hd = 0.0f;

#pragma unroll
    for (int k = 0; k < 2; ++k) {
        float m = X[k][0];
#pragma unroll
        for (int c = 1; c < 8; ++c) m = fmaxf(m, X[k][c]);
        float e[8]; float S = 0.f;
#pragma unroll
        for (int c = 0; c < 8; ++c) { e[c] = exp2f((X[k][c] - m) * 1.4426950408889634f); S += e[c]; }
        float r = 1.0f / S;
        int t = T[k];
        float xt = X[k][0];
#pragma unroll
        for (int c = 0; c < 8; ++c) {
            float pr = e[c] * r;
            sP[c] += pr;
            bool is = (c == t);
            tp[c] += is ? pr : 0.0f;
            cn[c] += is ? 1.0f : 0.0f;
            xt     = is ? X[k][c] : xt;
        }
        ce += (m - xt) + __log2f(S) * 0.69314718055994531f;
    }

    // HD: per mask, full channel-axis min-plus (branchless, exact) then accumulate.
    // pred_dt^2 = d_fg + d_bg exactly (one of the pair is 0 at every voxel).
#pragma unroll
    for (int mk = 0; mk < 4; ++mk) {
        float A[2][8];
#pragma unroll
        for (int c = 0; c < 8; ++c) {
            float2 t2 = *(const float2*)(g_f + (size_t)(mk * 16 + b * 8 + c) * NV + v);
            A[0][c] = t2.x; A[1][c] = t2.y;
        }
#pragma unroll
        for (int k = 0; k < 2; ++k) {
            float dch[8];
            minplus8(A[k], dch);
            int t = T[k];
#pragma unroll
            for (int c = 0; c < 8; ++c) {
                float toh = (t == c) ? 1.0f : 0.0f;
                float pe = X[k][c] - toh;
                hd += pe * pe * dch[c];
            }
        }
    }

    // warp reduce 26 scalars, then block-stage in smem, then 26 atomics per block
    __shared__ float sred[26 * 8];
    int w = threadIdx.x >> 5;
#pragma unroll
    for (int c = 0; c < 8; ++c) {
        float a  = warpsum(tp[c]);
        float s2 = warpsum(sP[c]);
        float q  = warpsum(cn[c]);
        if ((threadIdx.x & 31) == 0) {
            sred[c * 8 + w]        = a;
            sred[(8 + c) * 8 + w]  = s2;
            sred[(16 + c) * 8 + w] = q;
        }
    }
    float cs = warpsum(ce);
    float hs = warpsum(hd);
    if ((threadIdx.x & 31) == 0) { sred[24 * 8 + w] = cs; sred[25 * 8 + w] = hs; }
    __syncthreads();
    if (threadIdx.x < 26) {
        int i = threadIdx.x;
        float s = 0.f;
#pragma unroll
        for (int ww = 0; ww < 8; ++ww) s += sred[i * 8 + ww];
        float* dst;
        if (i < 8)       dst = &g_acc[b * 8 + i];
        else if (i < 16) dst = &g_acc[16 + b * 8 + (i - 8)];
        else if (i < 24) dst = &g_acc[32 + b * 8 + (i - 16)];
        else if (i == 24) dst = &g_acc[48];
        else              dst = &g_acc[49];
        atomicAdd(dst, s);
    }

    // last block finalizes (threadfence + completion counter)
    __threadfence();
    __syncthreads();
    if (threadIdx.x == 0) {
        unsigned done = atomicAdd(&g_cnt, 1u);
        if (done == gridDim.x - 1) {
            __threadfence();
            float diceAcc = 0.0f;
#pragma unroll
            for (int c = 1; c < 8; ++c) {
                float sb = 0.0f;
#pragma unroll
                for (int bb = 0; bb < 2; ++bb) {
                    float tps = g_acc[bb * 8 + c];
                    float sp  = g_acc[16 + bb * 8 + c];
                    float cnt = g_acc[32 + bb * 8 + c];
                    sb += 2.0f * tps / (sp + cnt + 1e-5f);   // alpha=beta=1
                }
                diceAcc += 0.5f * sb;
            }
            float dice = 1.0f - diceAcc * (1.0f / 7.0f);
            float cef = g_acc[48] * (1.0f / 524288.0f);
            float hdf = g_acc[49] * (1.0f / 4194304.0f);
            out[0] = dice + cef + hdf;
        }
    }
}

extern "C" void kernel_launch(void* const* d_in, const int* in_sizes, int n_in,
                              void* d_out, int out_size) {
    const float* in = (const float*)d_in[0];
    const int*   tg = (const int*)d_in[1];
    float* out = (float*)d_out;
    k_pass1 <<<1024, 256>>>(in, tg);
    k_pass23<<<2048, 256>>>();
    k_shd   <<<1024, 256>>>(in, tg, out);
}

// round 12
// speedup vs baseline: 1.0665x; 1.0665x over previous
#include <cuda_runtime.h>

#define NV 262144            // 64*64*64
#define BIGF 1e9f

// scratch: combined SIGNED fields, slots [field(2)][bc(16)][voxel]:
//   s = d_fg - d_bg, where at every voxel exactly one of (d_fg, d_bg) is 0.
//   This invariant holds after the X pass AND is preserved by the Y/Z passes
//   (a zero arises only from the voxel's own mask membership).
__device__ float g_f[64ull * NV];
__device__ float g_acc[64];
__device__ unsigned g_cnt;

__device__ __forceinline__ float warpsum(float v) {
#pragma unroll
    for (int o = 16; o > 0; o >>= 1) v += __shfl_xor_sync(0xffffffffu, v, o);
    return v;
}

// squared dist to nearest set bit of `zeros` (BIGF if none)
__device__ __forceinline__ float dt1(unsigned long long zeros, int x) {
    unsigned long long below = zeros << (63 - x);      // bits <= x
    int dfwd = below ? __clzll((long long)below) : 1000;
    unsigned long long above = zeros >> x;             // bits >= x
    int dbwd = above ? (__ffsll((long long)above) - 1) : 1000;
    int d = min(dfwd, dbwd);
    return (d > 63) ? BIGF : (float)(d * d);
}

// ---------------- pass 1 (axis X) ----------------
// 1024 blocks x 256 threads. Block = one (b,c,y) group of 64 z-lines.
// Writes signed combined field into slot field*16+bc (field 0=pred, 1=tgt).
__global__ void __launch_bounds__(256) k_pass1(const float* __restrict__ in, const int* __restrict__ tg) {
    if (blockIdx.x == 0) {       // reset accumulators for this replay
        if (threadIdx.x < 64) g_acc[threadIdx.x] = 0.0f;
        if (threadIdx.x == 64) g_cnt = 0u;
    }
    unsigned g = blockIdx.x;                 // (b,c,y)
    unsigned y = g & 63u, c = (g >> 6) & 7u, b = g >> 9;
    unsigned bc = b * 8u + c;
    int t = threadIdx.x;
    int z = t & 63;
    int part = t >> 6;                       // 0..3
    const float* pin = in + (size_t)bc * NV + y * 64u + z;
    const int*   ptg = tg + (size_t)b  * NV + y * 64u + z;

    unsigned m16 = 0u;                       // low 16: pred, high 16: tgt
#pragma unroll
    for (int k = 0; k < 16; ++k) {
        int x = part * 16 + k;
        float v = pin[(size_t)x * 4096];
        int   tt = ptg[(size_t)x * 4096];
        if (v > 0.5f)          m16 |= 1u << k;
        if ((unsigned)tt == c) m16 |= 1u << (16 + k);
    }
    __shared__ unsigned sm[256];
    sm[t] = m16;
    __syncthreads();

    int field = part & 1;                    // 0 = pred, 1 = tgt
    int half  = part >> 1;                   // x in [32*half, 32*half+32)
    unsigned long long m = 0ull;
#pragma unroll
    for (int p = 0; p < 4; ++p) {
        unsigned w = sm[z + p * 64];
        unsigned h16 = field ? (w >> 16) : (w & 0xFFFFu);
        m |= (unsigned long long)h16 << (16 * p);
    }
    float* o = g_f + (size_t)(field * 16 + bc) * NV + y * 64u + z;
#pragma unroll 4
    for (int k = 0; k < 32; ++k) {
        int x = half * 32 + k;
        bool bit = ((m >> x) & 1ull) != 0ull;
        unsigned long long zz = bit ? ~m : m;        // zeros of the non-trivial side
        float dsq = dt1(zz, x);                      // always > 0
        o[(size_t)x * 4096] = bit ? dsq : -dsq;      // s = d_fg - d_bg
    }
}

// ---------------- fused Y+Z min-plus over one (y,z) plane in smem ----------------
// Exact: windowed min, pairs |i-j|<=3 (off^2<=9). If windowed min <= 16 it is
// the true min (outside pairs contribute >= 16); otherwise full-scan fallback.
template<int LSTRIDE, int LANESTRIDE>
__device__ __forceinline__ void pass_line(float* s, int t) {
    int lane = t & 63;           // orthogonal coordinate
    int h = t >> 6;              // 0..3 -> outputs i in [16h, 16h+16)
    float* bp = s + lane * LANESTRIDE;
    int jbase = 16 * h - 3;
    float fv[22];
#pragma unroll
    for (int k = 0; k < 22; ++k) {
        int j = jbase + k;
        fv[k] = (j >= 0 && j < 64) ? bp[j * LSTRIDE] : 3.0e38f;
    }
    float d[16];
#pragma unroll
    for (int a = 0; a < 16; ++a) d[a] = 3.0e38f;
#pragma unroll
    for (int k = 0; k < 14; ++k) {
#pragma unroll
        for (int a = 0; a < 8; ++a) {
            const int off = a + 3 - k;
            if (off * off <= 9) d[a] = fminf(d[a], fv[k] + (float)(off * off));
        }
    }
#pragma unroll
    for (int k = 8; k < 22; ++k) {
#pragma unroll
        for (int a = 8; a < 16; ++a) {
            const int off = a + 3 - k;
            if (off * off <= 9) d[a] = fminf(d[a], fv[k] + (float)(off * off));
        }
    }
    float mxA = d[0], mxB = d[8];
#pragma unroll
    for (int a = 1; a < 8; ++a) { mxA = fmaxf(mxA, d[a]); mxB = fmaxf(mxB, d[a + 8]); }
    if (mxA > 16.0f) {
#pragma unroll 1
        for (int j = 0; j < 64; ++j) {
            float fj = bp[j * LSTRIDE];
#pragma unroll
            for (int a = 0; a < 8; ++a) { int dd = 16 * h + a - j; d[a] = fminf(d[a], fj + (float)(dd * dd)); }
        }
    }
    if (mxB > 16.0f) {
#pragma unroll 1
        for (int j = 0; j < 64; ++j) {
            float fj = bp[j * LSTRIDE];
#pragma unroll
            for (int a = 8; a < 16; ++a) { int dd = 16 * h + a - j; d[a] = fminf(d[a], fj + (float)(dd * dd)); }
        }
    }
    __syncthreads();   // all reads (incl. fallback) done before anyone writes
#pragma unroll
    for (int a = 0; a < 16; ++a) bp[(16 * h + a) * LSTRIDE] = d[a];
    __syncthreads();
}

// 2048 blocks: (cvol = field*16+bc in 0..31) x (x in 0..63).
// Reads ONE combined signed plane, splits to fg/bg, runs Y+Z passes on both,
// re-encodes s = d_fg - d_bg (exactly one side nonzero) and writes IN PLACE.
__global__ void __launch_bounds__(256) k_pass23() {
    __shared__ float sf[64 * 65];
    __shared__ float sb[64 * 65];
    unsigned x = blockIdx.x & 63u, cvol = blockIdx.x >> 6;   // cvol < 32
    float* gio = g_f + (size_t)cvol * NV + x * 4096u;        // combined plane
    int t = threadIdx.x;
    {
        const float4* g4 = (const float4*)gio;
#pragma unroll
        for (int m = 0; m < 4; ++m) {
            int e4 = m * 256 + t;            // 1024 float4s
            float4 val = g4[e4];
            int e = e4 * 4;
            int y = e >> 6, z = e & 63;
            int idx = y * 65 + z;
            sf[idx + 0] = fmaxf(val.x, 0.0f); sb[idx + 0] = fmaxf(-val.x, 0.0f);
            sf[idx + 1] = fmaxf(val.y, 0.0f); sb[idx + 1] = fmaxf(-val.y, 0.0f);
            sf[idx + 2] = fmaxf(val.z, 0.0f); sb[idx + 2] = fmaxf(-val.z, 0.0f);
            sf[idx + 3] = fmaxf(val.w, 0.0f); sb[idx + 3] = fmaxf(-val.w, 0.0f);
        }
    }
    __syncthreads();
    pass_line<65, 1>(sf, t);   // Y pass, fg
    pass_line<65, 1>(sb, t);   // Y pass, bg
    pass_line<1, 65>(sf, t);   // Z pass, fg
    pass_line<1, 65>(sb, t);   // Z pass, bg
    {
        float4* g4 = (float4*)gio;
#pragma unroll
        for (int m = 0; m < 4; ++m) {
            int e4 = m * 256 + t;
            int e = e4 * 4;
            int y = e >> 6, z = e & 63;
            int idx = y * 65 + z;
            float4 val;
            val.x = sf[idx + 0] - sb[idx + 0];
            val.y = sf[idx + 1] - sb[idx + 1];
            val.z = sf[idx + 2] - sb[idx + 2];
            val.w = sf[idx + 3] - sb[idx + 3];
            g4[e4] = val;
        }
    }
}

// ---------------- full min-plus over channel axis, length 8, branchless ----------------
__device__ __forceinline__ void minplus8(const float* __restrict__ a, float* __restrict__ d) {
#pragma unroll
    for (int i = 0; i < 8; ++i) {
        float m = 3.0e38f;
#pragma unroll
        for (int j = 0; j < 8; ++j) {
            const float q = (float)((i - j) * (i - j));
            m = fminf(m, a[j] + q);
        }
        d[i] = m;
    }
}

// ---------------- fused stats + HD (+ channel EDT pass) + final ----------------
// 1024 blocks x 256 threads x 2 voxels = 524288 (b, voxel) entries
__global__ void __launch_bounds__(256) k_shd(const float* __restrict__ in, const int* __restrict__ tg,
                                             float* __restrict__ out) {
    unsigned E = (blockIdx.x * 256u + threadIdx.x) * 2u;
    unsigned v = E & (NV - 1u);
    unsigned b = E >> 18;

    float X[2][8];
#pragma unroll
    for (int c = 0; c < 8; ++c) {
        float2 t2 = *(const float2*)(in + (size_t)(b * 8 + c) * NV + v);
        X[0][c] = t2.x; X[1][c] = t2.y;
    }
    int T[2];
    { int2 tt = *(const int2*)(tg + (size_t)b * NV + v); T[0] = tt.x; T[1] = tt.y; }

    float tp[8], sP[8], cn[8];
#pragma unroll
    for (int c = 0; c < 8; ++c) { tp[c] = 0.f; sP[c] = 0.f; cn[c] = 0.f; }
    float ce = 0.0f, hd = 0.0f;

#pragma unroll
    for (int k = 0; k < 2; ++k) {
        float m = X[k][0];
#pragma unroll
        for (int c = 1; c < 8; ++c) m = fmaxf(m, X[k][c]);
        float e[8]; float S = 0.f;
#pragma unroll
        for (int c = 0; c < 8; ++c) { e[c] = exp2f((X[k][c] - m) * 1.4426950408889634f); S += e[c]; }
        float r = 1.0f / S;
        int t = T[k];
        float xt = X[k][0];
#pragma unroll
        for (int c = 0; c < 8; ++c) {
            float pr = e[c] * r;
            sP[c] += pr;
            bool is = (c == t);
            tp[c] += is ? pr : 0.0f;
            cn[c] += is ? 1.0f : 0.0f;
            xt     = is ? X[k][c] : xt;
        }
        ce += (m - xt) + __log2f(S) * 0.69314718055994531f;
    }

    // HD: per field (pred, tgt), decode combined signed field into fg/bg,
    // full channel-axis min-plus on each (branchless, exact), accumulate
    // pe^2 * (d_fg + d_bg)  [pred_dt^2 = d_fg + d_bg since cross term is 0].
#pragma unroll
    for (int field = 0; field < 2; ++field) {
        float A[2][8];
#pragma unroll
        for (int c = 0; c < 8; ++c) {
            float2 t2 = *(const float2*)(g_f + (size_t)(field * 16 + b * 8 + c) * NV + v);
            A[0][c] = t2.x; A[1][c] = t2.y;
        }
#pragma unroll
        for (int k = 0; k < 2; ++k) {
            float fgv[8], bgv[8];
#pragma unroll
            for (int c = 0; c < 8; ++c) {
                fgv[c] = fmaxf(A[k][c], 0.0f);
                bgv[c] = fmaxf(-A[k][c], 0.0f);
            }
            float dfg[8], dbg[8];
            minplus8(fgv, dfg);
            minplus8(bgv, dbg);
            int t = T[k];
#pragma unroll
            for (int c = 0; c < 8; ++c) {
                float toh = (t == c) ? 1.0f : 0.0f;
                float pe = X[k][c] - toh;
                hd += pe * pe * (dfg[c] + dbg[c]);
            }
        }
    }

    // warp reduce 26 scalars, then block-stage in smem, then 26 atomics per block
    __shared__ float sred[26 * 8];
    int w = threadIdx.x >> 5;
#pragma unroll
    for (int c = 0; c < 8; ++c) {
        float a  = warpsum(tp[c]);
        float s2 = warpsum(sP[c]);
        float q  = warpsum(cn[c]);
        if ((threadIdx.x & 31) == 0) {
            sred[c * 8 + w]        = a;
            sred[(8 + c) * 8 + w]  = s2;
            sred[(16 + c) * 8 + w] = q;
        }
    }
    float cs = warpsum(ce);
    float hs = warpsum(hd);
    if ((threadIdx.x & 31) == 0) { sred[24 * 8 + w] = cs; sred[25 * 8 + w] = hs; }
    __syncthreads();
    if (threadIdx.x < 26) {
        int i = threadIdx.x;
        float s = 0.f;
#pragma unroll
        for (int ww = 0; ww < 8; ++ww) s += sred[i * 8 + ww];
        float* dst;
        if (i < 8)       dst = &g_acc[b * 8 + i];
        else if (i < 16) dst = &g_acc[16 + b * 8 + (i - 8)];
        else if (i < 24) dst = &g_acc[32 + b * 8 + (i - 16)];
        else if (i == 24) dst = &g_acc[48];
        else              dst = &g_acc[49];
        atomicAdd(dst, s);
    }

    // last block finalizes (threadfence + completion counter)
    __threadfence();
    __syncthreads();
    if (threadIdx.x == 0) {
        unsigned done = atomicAdd(&g_cnt, 1u);
        if (done == gridDim.x - 1) {
            __threadfence();
            float diceAcc = 0.0f;
#pragma unroll
            for (int c = 1; c < 8; ++c) {
                float sb = 0.0f;
#pragma unroll
                for (int bb = 0; bb < 2; ++bb) {
                    float tps = g_acc[bb * 8 + c];
                    float sp  = g_acc[16 + bb * 8 + c];
                    float cnt = g_acc[32 + bb * 8 + c];
                    sb += 2.0f * tps / (sp + cnt + 1e-5f);   // alpha=beta=1
                }
                diceAcc += 0.5f * sb;
            }
            float dice = 1.0f - diceAcc * (1.0f / 7.0f);
            float cef = g_acc[48] * (1.0f / 524288.0f);
            float hdf = g_acc[49] * (1.0f / 4194304.0f);
            out[0] = dice + cef + hdf;
        }
    }
}

extern "C" void kernel_launch(void* const* d_in, const int* in_sizes, int n_in,
                              void* d_out, int out_size) {
    const float* in = (const float*)d_in[0];
    const int*   tg = (const int*)d_in[1];
    float* out = (float*)d_out;
    k_pass1 <<<1024, 256>>>(in, tg);
    k_pass23<<<2048, 256>>>();
    k_shd   <<<1024, 256>>>(in, tg, out);
}